// round 9
// baseline (speedup 1.0000x reference)
#include <cuda_runtime.h>
#include <math_constants.h>

// Scratch + sync state (no dynamic allocation allowed; zero-init at load,
// reset by the last-retiring block for graph replays).
__device__ float g_P4[2 * 256];          // maxpool16(x4)  [b, hw]
__device__ float g_T3[2 * 256 * 256];    // maxpool8(x3)   [b, j, hw]
__device__ int   g_t3flag[512];          // per-plane ready flag [b*256+j]
__device__ int   g_p4cnt[2];             // per-batch P4 values completed (==256)
__device__ int   g_finish = 0;           // blocks completed (for replay reset)

#define N_PRO   512                       // prologue blocks (x3 plane + 1 P4 val)
#define N_MAIN  8192                      // main blocks
#define N_TOTAL (N_PRO + N_MAIN)

// ---------------------------------------------------------------------------
// Single fused kernel, grid = 8704 x 256.
//   bid [0, 512): prologue block (b = bid>>8, j = p = bid&255):
//       - one x4 16x16 window -> P4[b, p]   (1 load/thread + tree reduce)
//       - maxpool8 of x3 plane (b, j) -> T3 (16 float4 loads/thread)
//       - fence; atomicAdd(g_p4cnt[b]); g_t3flag[bid] = 1
//   bid [512, 8704): main block (b, k): pool x2/x1 into registers (overlaps
//       with prologue HBM traffic), t0 polls ONLY plane (b, k&255) flag and
//       g_p4cnt[b]==256, then combines with T3/P4 and streams ff/out.
// Prologue bids 0..511 dispatch first into wave 1 (~1184 slots) -> deadlock-
// free; ~672 main blocks now prefetch during the x3 window (vs 160 before).
// Last finishing block clears all sync state so graph replays start clean.
// ---------------------------------------------------------------------------
__global__ void __launch_bounds__(256) fused_all_kernel(
        const float* __restrict__ x1, const float* __restrict__ x2,
        const float* __restrict__ x3, const float* __restrict__ x4,
        const float* __restrict__ ff, float* __restrict__ out) {
    const int bid = blockIdx.x;
    const int t   = threadIdx.x;

    if (bid < N_PRO) {
        // ================= prologue block =================
        const int b  = bid >> 8;             // batch
        const int j  = bid & 255;            // x3 channel == P4 output pixel
        const int oh = t >> 4, ow = t & 15;

        // ---- x4: one 16x16 window for P4[b, j] (issued first, tiny) ----
        const int poh = j >> 4, pow_ = j & 15;
        const float xv = x4[(size_t)b * 65536
                            + (16 * poh + (t >> 4)) * 256 + 16 * pow_ + (t & 15)];

        // ---- maxpool8 of x3 plane (b, j) ----
        const float* base = x3 + ((size_t)b * 256 + j) * 16384;
        float m = -CUDART_INF_F;
#pragma unroll
        for (int r = 0; r < 8; ++r) {
            const float4* row = (const float4*)(base + (8 * oh + r) * 128 + 8 * ow);
            float4 v0 = row[0];
            float4 v1 = row[1];
            m = fmaxf(m, fmaxf(fmaxf(v0.x, v0.y), fmaxf(v0.z, v0.w)));
            m = fmaxf(m, fmaxf(fmaxf(v1.x, v1.y), fmaxf(v1.z, v1.w)));
        }
        g_T3[((size_t)bid) * 256 + t] = m;

        // ---- reduce x4 window to one value ----
        __shared__ float red[8];
        float v = xv;
#pragma unroll
        for (int s = 16; s > 0; s >>= 1)
            v = fmaxf(v, __shfl_down_sync(0xFFFFFFFFu, v, s));
        if ((t & 31) == 0) red[t >> 5] = v;
        __syncthreads();
        if (t == 0) {
            float pm = red[0];
#pragma unroll
            for (int w = 1; w < 8; ++w) pm = fmaxf(pm, red[w]);
            g_P4[b * 256 + j] = pm;
            __threadfence();                 // release T3 plane + P4 value
            atomicAdd(&g_p4cnt[b], 1);
            *(volatile int*)&g_t3flag[bid] = 1;
        }
    } else {
        // ================= main block =================
        const int B  = bid - N_PRO;          // [0, 8192)
        const int b  = B >> 12, k = B & 4095;
        const int oh = t >> 4, ow = t & 15;

        // ---- prologue-independent HBM reads (overlap with prologue) ----
        const float* x2p = x2 + ((size_t)b * 4096 + k) * 4096;
        float p2 = -CUDART_INF_F;
#pragma unroll
        for (int r = 0; r < 4; ++r) {
            float4 v = *(const float4*)(x2p + (4 * oh + r) * 64 + 4 * ow);
            p2 = fmaxf(p2, fmaxf(fmaxf(v.x, v.y), fmaxf(v.z, v.w)));
        }

        float p1v[4];
#pragma unroll
        for (int m = 0; m < 4; ++m) {
            const int c = k + 4096 * m;
            const float* x1p = x1 + ((size_t)b * 16384 + c) * 1024;
            float2 a0 = *(const float2*)(x1p + (2 * oh)     * 32 + 2 * ow);
            float2 a1 = *(const float2*)(x1p + (2 * oh + 1) * 32 + 2 * ow);
            p1v[m] = fmaxf(fmaxf(a0.x, a0.y), fmaxf(a1.x, a1.y));
        }

        // ---- fine-grained wait: only MY plane + MY batch's P4 ----
        const int plane = (b << 8) | (k & 255);
        if (t == 0) {
            while (*(volatile int*)&g_t3flag[plane] == 0) __nanosleep(128);
            while (*(volatile int*)&g_p4cnt[b] < 256)     __nanosleep(128);
            __threadfence();                 // acquire
        }
        __syncthreads();                     // block-wide release of the wait

        const float basev = p2
                          + g_T3[((size_t)plane) * 256 + t]
                          + g_P4[b * 256 + t];

#pragma unroll
        for (int m = 0; m < 4; ++m) {
            const int c = k + 4096 * m;
            const float s = basev + p1v[m];
            const size_t o0 = ((size_t)b * 32768 + c) * 256 + t;
            const size_t o1 = o0 + (size_t)16384 * 256;
            out[o0] = fmaxf(s + ff[o0], 0.0f);
            out[o1] = fmaxf(s + ff[o1], 0.0f);
        }
    }

    // ---- replay-safe reset: last-retiring block clears all sync state ----
    __shared__ int is_last;
    __syncthreads();
    if (t == 0) {
        const int old = atomicAdd(&g_finish, 1);
        is_last = (old == N_TOTAL - 1);
    }
    __syncthreads();
    if (is_last) {
        g_t3flag[t]       = 0;
        g_t3flag[t + 256] = 0;
        if (t < 2) g_p4cnt[t] = 0;
        if (t == 0) {
            g_finish = 0;
            __threadfence();
        }
    }
}

// ---------------------------------------------------------------------------
// Launch: inputs in metadata order: x1, x2, x3, x4, pure_ff
// ---------------------------------------------------------------------------
extern "C" void kernel_launch(void* const* d_in, const int* in_sizes, int n_in,
                              void* d_out, int out_size) {
    const float* x1 = (const float*)d_in[0];
    const float* x2 = (const float*)d_in[1];
    const float* x3 = (const float*)d_in[2];
    const float* x4 = (const float*)d_in[3];
    const float* ff = (const float*)d_in[4];
    float* out = (float*)d_out;

    fused_all_kernel<<<N_TOTAL, 256>>>(x1, x2, x3, x4, ff, out);
}

// round 10
// speedup vs baseline: 1.0889x; 1.0889x over previous
#include <cuda_runtime.h>
#include <math_constants.h>

// Scratch + sync state (no dynamic allocation allowed).
__device__ float g_P4[2 * 256];          // maxpool16(x4)  [b, hw]
__device__ float g_T3[2 * 256 * 256];    // maxpool8(x3)   [b, j, hw]
__device__ int   g_done   = 0;           // prologue blocks completed
__device__ int   g_finish = 0;           // blocks completed (for replay reset)

#define N_PRO   1024                      // prologue blocks (512 x3 + 512 x4)
#define N_MAIN  8192                      // main blocks
#define N_TOTAL (N_PRO + N_MAIN)

// ---------------------------------------------------------------------------
// Single fused kernel, grid = 9216 x 256  (best-known R6 skeleton + full read
// prefetch: ALL prologue-independent reads — x2, x1 AND ff — are issued
// before the wait, so HBM read traffic never stalls on the barrier; the
// post-wait segment is compute + stores only).
//   bid [0, 512):     T3[b, j, hw] = maxpool8(x3[b,j])   (x3: [2,256,128,128])
//   bid [512, 1024):  P4[b, hw]    = maxpool16(x4[b,0])  (x4: [2,1,256,256])
//     both release-signal g_done.
//   bid [1024, 9216): main block (b, k): prefetch x2/x1/ff into registers,
//     t0-only spin on g_done==N_PRO, combine with T3/P4, store out.
// Deadlock-free at any occupancy: prologue bids precede all main bids in the
// in-order dispatcher and prologue blocks never wait.
// Last finishing block resets counters so graph replays start clean.
// ---------------------------------------------------------------------------
__global__ void __launch_bounds__(256) fused_all_kernel(
        const float* __restrict__ x1, const float* __restrict__ x2,
        const float* __restrict__ x3, const float* __restrict__ x4,
        const float* __restrict__ ff, float* __restrict__ out) {
    const int bid = blockIdx.x;
    const int t   = threadIdx.x;

    if (bid < N_PRO) {
        if (bid < 512) {
            // ---- maxpool8 of one full x3 plane ----
            const int b  = bid >> 8, j = bid & 255;
            const int oh = t >> 4, ow = t & 15;
            const float* base = x3 + ((size_t)b * 256 + j) * 16384;
            float m = -CUDART_INF_F;
#pragma unroll
            for (int r = 0; r < 8; ++r) {
                const float4* row = (const float4*)(base + (8 * oh + r) * 128 + 8 * ow);
                float4 v0 = row[0];
                float4 v1 = row[1];
                m = fmaxf(m, fmaxf(fmaxf(v0.x, v0.y), fmaxf(v0.z, v0.w)));
                m = fmaxf(m, fmaxf(fmaxf(v1.x, v1.y), fmaxf(v1.z, v1.w)));
            }
            g_T3[((size_t)b * 256 + j) * 256 + t] = m;
        } else {
            // ---- maxpool16 of x4: one output value per block, tree reduce ----
            const int o  = bid - 512;          // [0, 512)
            const int b  = o >> 8;
            const int p  = o & 255;
            const int oh = p >> 4, ow = p & 15;
            const float* base = x4 + (size_t)b * 65536;
            float v = base[(16 * oh + (t >> 4)) * 256 + 16 * ow + (t & 15)];

            __shared__ float red[8];
#pragma unroll
            for (int s = 16; s > 0; s >>= 1)
                v = fmaxf(v, __shfl_down_sync(0xFFFFFFFFu, v, s));
            if ((t & 31) == 0) red[t >> 5] = v;
            __syncthreads();
            if (t == 0) {
                float m = red[0];
#pragma unroll
                for (int w = 1; w < 8; ++w) m = fmaxf(m, red[w]);
                g_P4[b * 256 + p] = m;
            }
        }
        // Release: this block's T3/P4 writes become visible, then count.
        __syncthreads();
        if (t == 0) {
            __threadfence();
            atomicAdd(&g_done, 1);
        }
    } else {
        // ================= main block =================
        const int B  = bid - N_PRO;            // [0, 8192)
        const int b  = B >> 12, k = B & 4095;
        const int oh = t >> 4, ow = t & 15;

        // ---- prologue-independent HBM reads: x2 pool4 ----
        const float* x2p = x2 + ((size_t)b * 4096 + k) * 4096;
        float p2 = -CUDART_INF_F;
#pragma unroll
        for (int r = 0; r < 4; ++r) {
            float4 v = *(const float4*)(x2p + (4 * oh + r) * 64 + 4 * ow);
            p2 = fmaxf(p2, fmaxf(fmaxf(v.x, v.y), fmaxf(v.z, v.w)));
        }

        // ---- prologue-independent HBM reads: x1 pool2 (4 aliases) ----
        float p1v[4];
#pragma unroll
        for (int m = 0; m < 4; ++m) {
            const int c = k + 4096 * m;
            const float* x1p = x1 + ((size_t)b * 16384 + c) * 1024;
            float2 a0 = *(const float2*)(x1p + (2 * oh)     * 32 + 2 * ow);
            float2 a1 = *(const float2*)(x1p + (2 * oh + 1) * 32 + 2 * ow);
            p1v[m] = fmaxf(fmaxf(a0.x, a0.y), fmaxf(a1.x, a1.y));
        }

        // ---- prologue-independent HBM reads: ff (both tile halves) ----
        const size_t obase = ((size_t)b * 32768 + k) * 256 + t;
        float f0[4], f1[4];
#pragma unroll
        for (int m = 0; m < 4; ++m) {
            const size_t o0 = obase + (size_t)(4096 * m) * 256;
            f0[m] = ff[o0];
            f1[m] = ff[o0 + (size_t)16384 * 256];
        }

        // ---- wait for prologue: ONLY t==0 polls (no L2 spin-storm) ----
        if (t == 0) {
            if (*(volatile int*)&g_done < N_PRO) {
                while (*(volatile int*)&g_done < N_PRO) __nanosleep(256);
            }
            __threadfence();                   // acquire side
        }
        __syncthreads();                       // block-wide release of the wait

        const float basev = p2
                          + g_T3[((size_t)b * 256 + (k & 255)) * 256 + t]
                          + g_P4[b * 256 + t];

        // ---- stores only (all reads already in registers) ----
#pragma unroll
        for (int m = 0; m < 4; ++m) {
            const float s = basev + p1v[m];
            const size_t o0 = obase + (size_t)(4096 * m) * 256;
            out[o0]                        = fmaxf(s + f0[m], 0.0f);
            out[o0 + (size_t)16384 * 256]  = fmaxf(s + f1[m], 0.0f);
        }
    }

    // ---- replay-safe counter reset: last block of the grid cleans up ----
    __syncthreads();
    if (t == 0) {
        const int old = atomicAdd(&g_finish, 1);
        if (old == N_TOTAL - 1) {
            g_done   = 0;
            g_finish = 0;
            __threadfence();
        }
    }
}

// ---------------------------------------------------------------------------
// Launch: inputs in metadata order: x1, x2, x3, x4, pure_ff
// ---------------------------------------------------------------------------
extern "C" void kernel_launch(void* const* d_in, const int* in_sizes, int n_in,
                              void* d_out, int out_size) {
    const float* x1 = (const float*)d_in[0];
    const float* x2 = (const float*)d_in[1];
    const float* x3 = (const float*)d_in[2];
    const float* x4 = (const float*)d_in[3];
    const float* ff = (const float*)d_in[4];
    float* out = (float*)d_out;

    fused_all_kernel<<<N_TOTAL, 256>>>(x1, x2, x3, x4, ff, out);
}